// round 8
// baseline (speedup 1.0000x reference)
#include <cuda_runtime.h>

// COOTensorProduct: out[b, r] = sum_{c} outer(in1,in2)[b,c] * cb[r,c]
// CG block structure: each output row r = (l3, l1, l2, u, v, m3) reads only
// the (2l1+1)x(2l2+1) column block; all 16 (u,v) pairs of a (l1,l2,l3) group
// share one Wigner block W, gathered at runtime from cb's (u=0,v=0) block.
//
// R8 = R7 (fork-join concurrent big/small kernels, 36.9us) + scheduling:
//  - grid transposed to (x=group, y=batch) so every dispatch wave holds a
//    MIX of heavy and light groups;
//  - group tables sorted by descending cost (LPT) so the longest blocks
//    start first and don't form the tail.

#define CB_W 4096
#define OUT_W 4096

struct Group { int l1, l2, l3, gbase, o1, o2; };

// Layout validated by the R1 runtime-scan kernel (pass, rel_err 6e-8).
// Tables sorted by descending cost l3n*K1*K2P (LPT order).
#define N_SMALL 19
#define N_BIG   25
__constant__ Group GS[N_SMALL] = {
    {2,2,4,2640,16,16},  // 360
    {2,2,3,1824,16,16},  // 280
    {2,2,2, 976,16,16},  // 200
    {1,2,3,1488, 4,16},  // 168
    {2,1,3,1712,16, 4},  // 140
    {2,2,1, 304,16,16},  // 120
    {1,2,2, 656, 4,16},  // 120
    {2,1,2, 896,16, 4},  // 100
    {1,2,1, 208, 4,16},  //  72
    {1,1,2, 576, 4, 4},  //  60
    {2,1,1, 256,16, 4},  //  60
    {2,2,0,  32,16,16},  //  40
    {0,2,2, 496, 0,16},  //  40
    {1,1,1, 160, 4, 4},  //  36
    {2,0,2, 816,16, 0},  //  25
    {0,1,1,  64, 0, 4},  //  12
    {1,1,0,  16, 4, 4},  //  12
    {1,0,1, 112, 4, 0},  //   9
    {0,0,0,   0, 0, 0}   //   1
};
__constant__ Group GB[N_BIG] = {
    {3,3,6,3888,36,36},  // 728
    {3,3,5,3712,36,36},  // 616
    {3,2,5,3536,36,16},  // 616
    {3,3,4,3216,36,36},  // 504
    {3,2,4,3072,36,16},  // 504
    {2,3,5,3360,16,36},  // 440
    {3,3,3,2384,36,36},  // 392
    {3,2,3,2272,36,16},  // 392
    {2,3,4,2784,16,36},  // 360
    {3,3,2,1296,36,36},  // 280
    {3,2,2,1216,36,16},  // 280
    {2,3,3,1936,16,36},  // 280
    {3,1,4,2928,36, 4},  // 252
    {1,3,4,2496, 4,36},  // 216
    {2,3,2,1056,16,36},  // 200
    {3,1,3,2160,36, 4},  // 196
    {3,3,1, 448,36,36},  // 168
    {3,2,1, 400,36,16},  // 168
    {1,3,3,1600, 4,36},  // 168
    {3,1,2,1136,36, 4},  // 140
    {2,3,1, 352,16,36},  // 120
    {1,3,2, 736, 4,36},  // 120
    {3,3,0,  48,36,36},  //  56
    {0,3,3,1376, 0,36},  //  56
    {3,0,3,2048,36, 0}   //  49
};

// ---------------------------------------------------------------------------
// Block = 32 batch lanes x one group. v-split: warp w owns multiplicity
// column v=w and loops over ALL m3 rows -> perfect warp balance for any l3n.
// W stored K2P-padded in smem, read via LDS.128 (uniform broadcast).
// sout (plane-k layout, pad 33) is UNIONed with the sa staging buffer.
// ---------------------------------------------------------------------------
template <int L1, int L2>
__device__ __forceinline__ void run_group(
    const Group gr,
    const float* __restrict__ in1, const float* __restrict__ in2,
    const float* __restrict__ cb,
    float* __restrict__ out, int b0,
    float* sa, float* swp)
{
    constexpr int K1 = 2 * L1 + 1, K2 = 2 * L2 + 1;
    constexpr int C1 = 4 * K1, C2 = 4 * K2;
    constexpr int Q1 = C1 / 4, Q2 = C2 / 4;
    constexpr int K2P = (K2 == 1) ? 1 : ((K2 + 3) & ~3);   // 1,4,8
    constexpr int WROW = K1 * K2P;

    float* sa1  = sa;            // [C1*32]
    float* sa2  = sa + C1 * 32;  // [C2*32]
    float* sout = sa;            // union: alive after registers loaded

    const int tid  = threadIdx.x;
    const int lane = tid & 31;
    const int warp = tid >> 5;   // = v
    const int l3n  = 2 * gr.l3 + 1;

    // ---- stage inputs via float4 (o1/o2 are multiples of 4) ----
    {
        const float4* p1 = reinterpret_cast<const float4*>(in1) + (size_t)b0 * 16 + (gr.o1 >> 2);
        for (int x = tid; x < 32 * Q1; x += 128) {
            int b = x / Q1, q = x - b * Q1;              // compile-time divisor
            float4 v = p1[(size_t)b * 16 + q];
            sa1[(4 * q + 0) * 32 + b] = v.x;
            sa1[(4 * q + 1) * 32 + b] = v.y;
            sa1[(4 * q + 2) * 32 + b] = v.z;
            sa1[(4 * q + 3) * 32 + b] = v.w;
        }
        const float4* p2 = reinterpret_cast<const float4*>(in2) + (size_t)b0 * 16 + (gr.o2 >> 2);
        for (int x = tid; x < 32 * Q2; x += 128) {
            int b = x / Q2, q = x - b * Q2;
            float4 v = p2[(size_t)b * 16 + q];
            sa2[(4 * q + 0) * 32 + b] = v.x;
            sa2[(4 * q + 1) * 32 + b] = v.y;
            sa2[(4 * q + 2) * 32 + b] = v.z;
            sa2[(4 * q + 3) * 32 + b] = v.w;
        }
    }
    // ---- padded Wigner gather from cb (u=0,v=0 block); zeros in the pad ----
    for (int i = tid; i < l3n * WROW; i += 128) {
        int m3 = i / WROW;                               // compile-time divisor
        int r  = i - m3 * WROW;
        int m1 = r / K2P;
        int m2 = r - m1 * K2P;
        float wv = 0.f;
        if (m2 < K2)
            wv = cb[(size_t)(gr.gbase + m3) * CB_W + (gr.o1 + m1) * 64 + gr.o2 + m2];
        swp[i] = wv;
    }
    __syncthreads();

    // ---- registers: full a1 (4 u-blocks), only this warp's v-block of a2 ----
    float a1[C1];
#pragma unroll
    for (int c = 0; c < C1; c++) a1[c] = sa1[c * 32 + lane];
    float a2p[K2P];
#pragma unroll
    for (int j = 0; j < K2P; j++)
        a2p[j] = (j < K2) ? sa2[(warp * K2 + j) * 32 + lane] : 0.f;
    __syncthreads();   // sa dead -> sout (union) alive

    const int span4 = 4 * l3n;

    for (int m3 = 0; m3 < l3n; m3++) {
        const float* wr = swp + m3 * WROW;
        float acc0 = 0.f, acc1 = 0.f, acc2 = 0.f, acc3 = 0.f;
#pragma unroll
        for (int m1 = 0; m1 < K1; m1++) {
            float s = 0.f;
            if constexpr (K2P % 4 == 0) {
#pragma unroll
                for (int q = 0; q < K2P / 4; q++) {
                    float4 w4 = *reinterpret_cast<const float4*>(wr + m1 * K2P + 4 * q);
                    s += w4.x * a2p[4 * q + 0];
                    s += w4.y * a2p[4 * q + 1];
                    s += w4.z * a2p[4 * q + 2];
                    s += w4.w * a2p[4 * q + 3];
                }
            } else {
                s = wr[m1] * a2p[0];
            }
            acc0 += a1[0 * K1 + m1] * s;
            acc1 += a1[1 * K1 + m1] * s;
            acc2 += a1[2 * K1 + m1] * s;
            acc3 += a1[3 * K1 + m1] * s;
        }
        // rows r = (u*4 + v)*l3n + m3; plane-k staging (conflict-free STS)
        {
            int r, r4, k;
            r = (0 * 4 + warp) * l3n + m3; r4 = r >> 2; k = r & 3;
            sout[(k * span4 + r4) * 33 + lane] = acc0;
            r = (1 * 4 + warp) * l3n + m3; r4 = r >> 2; k = r & 3;
            sout[(k * span4 + r4) * 33 + lane] = acc1;
            r = (2 * 4 + warp) * l3n + m3; r4 = r >> 2; k = r & 3;
            sout[(k * span4 + r4) * 33 + lane] = acc2;
            r = (3 * 4 + warp) * l3n + m3; r4 = r >> 2; k = r & 3;
            sout[(k * span4 + r4) * 33 + lane] = acc3;
        }
    }
    __syncthreads();

    // ---- flat, near-division-free coalesced epilogue ----
    {
        const int total = 32 * span4;
        int b  = tid / span4;               // single runtime division
        int r4 = tid - b * span4;
        const int db = 128 / span4;         // block-uniform
        const int dr = 128 - db * span4;
        for (int i = tid; i < total; i += 128) {
            float4 v;
            v.x = sout[(0 * span4 + r4) * 33 + b];
            v.y = sout[(1 * span4 + r4) * 33 + b];
            v.z = sout[(2 * span4 + r4) * 33 + b];
            v.w = sout[(3 * span4 + r4) * 33 + b];
            *reinterpret_cast<float4*>(
                out + (size_t)(b0 + b) * OUT_W + gr.gbase + 4 * r4) = v;
            b += db; r4 += dr;
            if (r4 >= span4) { r4 -= span4; b++; }
        }
    }
}

// ---------------------------------------------------------------------------
__global__ void __launch_bounds__(128, 8)
tp_small(const float* __restrict__ in1, const float* __restrict__ in2,
         const float* __restrict__ cb, float* __restrict__ out)
{
    __shared__ float swp[360];         // max l3n*K1*K2P = 9*5*8 (2,2,4)
    __shared__ float ubuf[4752];       // max(sa 40*32, sout 144*33)

    const Group gr = GS[blockIdx.x];
    const int b0 = blockIdx.y * 32;

#define RG(A, B2) run_group<A, B2>(gr, in1, in2, cb, out, b0, ubuf, swp)
    switch (gr.l1 * 3 + gr.l2) {
        case 0: RG(0, 0); break;
        case 1: RG(0, 1); break;
        case 2: RG(0, 2); break;
        case 3: RG(1, 0); break;
        case 4: RG(1, 1); break;
        case 5: RG(1, 2); break;
        case 6: RG(2, 0); break;
        case 7: RG(2, 1); break;
        case 8: RG(2, 2); break;
    }
#undef RG
}

__global__ void __launch_bounds__(128, 7)
tp_big(const float* __restrict__ in1, const float* __restrict__ in2,
       const float* __restrict__ cb, float* __restrict__ out)
{
    __shared__ float swp[728];         // max l3n*K1*K2P = 13*7*8 (3,3,6)
    __shared__ float ubuf[6864];       // max(sa 56*32, sout 208*33)

    const Group gr = GB[blockIdx.x];
    const int b0 = blockIdx.y * 32;

#define RG(A, B2) run_group<A, B2>(gr, in1, in2, cb, out, b0, ubuf, swp)
    switch (gr.l1 * 4 + gr.l2) {
        case  3: RG(0, 3); break;
        case  7: RG(1, 3); break;
        case 11: RG(2, 3); break;
        case 12: RG(3, 0); break;
        case 13: RG(3, 1); break;
        case 14: RG(3, 2); break;
        case 15: RG(3, 3); break;
    }
#undef RG
}

// ---------------------------------------------------------------------------
// Fork-join launch: tp_big on the origin stream, tp_small on a forked
// stream, joined back -> two PARALLEL graph branches, concurrent execution.
// ---------------------------------------------------------------------------
extern "C" void kernel_launch(void* const* d_in, const int* in_sizes, int n_in,
                              void* d_out, int out_size)
{
    const float* in1 = (const float*)d_in[0];
    const float* in2 = (const float*)d_in[1];
    const float* cb  = (const float*)d_in[2];
    float* out = (float*)d_out;

    int B = in_sizes[0] / 64;

    cudaStream_t s2;
    cudaStreamCreateWithFlags(&s2, cudaStreamNonBlocking);
    cudaEvent_t eFork, eJoin;
    cudaEventCreateWithFlags(&eFork, cudaEventDisableTiming);
    cudaEventCreateWithFlags(&eJoin, cudaEventDisableTiming);

    cudaEventRecord(eFork, 0);
    cudaStreamWaitEvent(s2, eFork, 0);

    dim3 grid_big(N_BIG, B / 32);
    tp_big<<<grid_big, 128, 0, 0>>>(in1, in2, cb, out);
    dim3 grid_small(N_SMALL, B / 32);
    tp_small<<<grid_small, 128, 0, s2>>>(in1, in2, cb, out);

    cudaEventRecord(eJoin, s2);
    cudaStreamWaitEvent(0, eJoin, 0);

    cudaEventDestroy(eFork);
    cudaEventDestroy(eJoin);
    cudaStreamDestroy(s2);
}

// round 9
// speedup vs baseline: 1.0017x; 1.0017x over previous
#include <cuda_runtime.h>

// COOTensorProduct: out[b, r] = sum_{c} outer(in1,in2)[b,c] * cb[r,c]
// CG block structure: each output row r = (l3, l1, l2, u, v, m3) reads only
// the (2l1+1)x(2l2+1) column block; all 16 (u,v) pairs of a (l1,l2,l3) group
// share one Wigner block W, gathered at runtime from cb's (u=0,v=0) block.
//
// R9 = R8 (fork-join concurrent big/small, 36.9us) + f32x2-PACKED small
// kernel: each lane processes TWO batch elements (b, b+32) via
// fma.rn.f32x2 (Blackwell FFMA2) -> compute instructions ~halve, block
// count halves. Per-component rounding identical to scalar -> bitwise
// same results. Big kernel unchanged (packed variant would tank its occ).

#define CB_W 4096
#define OUT_W 4096

typedef unsigned long long u64t;

#define FMA2(d, a, b, c) \
    asm("fma.rn.f32x2 %0, %1, %2, %3;" : "=l"(d) : "l"(a), "l"(b), "l"(c))
#define MUL2(d, a, b) \
    asm("mul.rn.f32x2 %0, %1, %2;" : "=l"(d) : "l"(a), "l"(b))
#define UNPK2(lo, hi, p) \
    asm("mov.b64 {%0, %1}, %2;" : "=f"(lo), "=f"(hi) : "l"(p))

struct Group { int l1, l2, l3, gbase, o1, o2; };

// Layout validated by the R1 runtime-scan kernel (pass, rel_err 6e-8).
// Tables sorted by descending cost (LPT order).
#define N_SMALL 19
#define N_BIG   25
__constant__ Group GS[N_SMALL] = {
    {2,2,4,2640,16,16},{2,2,3,1824,16,16},{2,2,2, 976,16,16},
    {1,2,3,1488, 4,16},{2,1,3,1712,16, 4},{2,2,1, 304,16,16},
    {1,2,2, 656, 4,16},{2,1,2, 896,16, 4},{1,2,1, 208, 4,16},
    {1,1,2, 576, 4, 4},{2,1,1, 256,16, 4},{2,2,0,  32,16,16},
    {0,2,2, 496, 0,16},{1,1,1, 160, 4, 4},{2,0,2, 816,16, 0},
    {0,1,1,  64, 0, 4},{1,1,0,  16, 4, 4},{1,0,1, 112, 4, 0},
    {0,0,0,   0, 0, 0}
};
__constant__ Group GB[N_BIG] = {
    {3,3,6,3888,36,36},{3,3,5,3712,36,36},{3,2,5,3536,36,16},
    {3,3,4,3216,36,36},{3,2,4,3072,36,16},{2,3,5,3360,16,36},
    {3,3,3,2384,36,36},{3,2,3,2272,36,16},{2,3,4,2784,16,36},
    {3,3,2,1296,36,36},{3,2,2,1216,36,16},{2,3,3,1936,16,36},
    {3,1,4,2928,36, 4},{1,3,4,2496, 4,36},{2,3,2,1056,16,36},
    {3,1,3,2160,36, 4},{3,3,1, 448,36,36},{3,2,1, 400,36,16},
    {1,3,3,1600, 4,36},{3,1,2,1136,36, 4},{2,3,1, 352,16,36},
    {1,3,2, 736, 4,36},{3,3,0,  48,36,36},{0,3,3,1376, 0,36},
    {3,0,3,2048,36, 0}
};

// ===========================================================================
// PACKED small-group path: 64 batch rows per block, each lane holds the
// f32x2 pair (b0+lane, b0+32+lane). W duplicated {w,w} in smem. sout in
// two halves (lo = b<32, hi = b>=32), each the proven conflict-free
// plane-k layout (pad 33).
// ===========================================================================
template <int L1, int L2>
__device__ __forceinline__ void run_group_p2(
    const Group gr,
    const float* __restrict__ in1, const float* __restrict__ in2,
    const float* __restrict__ cb,
    float* __restrict__ out, int b0,
    float* sa, float* swp2, int halfOff)
{
    constexpr int K1 = 2 * L1 + 1, K2 = 2 * L2 + 1;
    constexpr int C1 = 4 * K1, C2 = 4 * K2;
    constexpr int Q1 = C1 / 4, Q2 = C2 / 4;
    constexpr int K2P = (K2 == 1) ? 1 : ((K2 + 3) & ~3);   // 1,4,8
    constexpr int WROW = K1 * K2P;

    float* sa1  = sa;            // [C1*64] packed cols
    float* sa2  = sa + C1 * 64;  // [C2*64]
    float* sout = sa;            // union after registers loaded

    const int tid  = threadIdx.x;
    const int lane = tid & 31;
    const int warp = tid >> 5;   // = v
    const int l3n  = 2 * gr.l3 + 1;

    // ---- stage inputs: packed column = 2*(b&31) + (b>>5) ----
    {
        const float4* p1 = reinterpret_cast<const float4*>(in1) + (size_t)b0 * 16 + (gr.o1 >> 2);
        for (int x = tid; x < 64 * Q1; x += 128) {
            int b = x / Q1, q = x - b * Q1;              // compile-time divisor
            float4 v = p1[(size_t)b * 16 + q];
            int col = 2 * (b & 31) + (b >> 5);
            sa1[(4 * q + 0) * 64 + col] = v.x;
            sa1[(4 * q + 1) * 64 + col] = v.y;
            sa1[(4 * q + 2) * 64 + col] = v.z;
            sa1[(4 * q + 3) * 64 + col] = v.w;
        }
        const float4* p2 = reinterpret_cast<const float4*>(in2) + (size_t)b0 * 16 + (gr.o2 >> 2);
        for (int x = tid; x < 64 * Q2; x += 128) {
            int b = x / Q2, q = x - b * Q2;
            float4 v = p2[(size_t)b * 16 + q];
            int col = 2 * (b & 31) + (b >> 5);
            sa2[(4 * q + 0) * 64 + col] = v.x;
            sa2[(4 * q + 1) * 64 + col] = v.y;
            sa2[(4 * q + 2) * 64 + col] = v.z;
            sa2[(4 * q + 3) * 64 + col] = v.w;
        }
    }
    // ---- duplicated Wigner gather: swp2[2i]=swp2[2i+1]=w_i ----
    for (int i = tid; i < l3n * WROW; i += 128) {
        int m3 = i / WROW;
        int r  = i - m3 * WROW;
        int m1 = r / K2P;
        int m2 = r - m1 * K2P;
        float wv = 0.f;
        if (m2 < K2)
            wv = cb[(size_t)(gr.gbase + m3) * CB_W + (gr.o1 + m1) * 64 + gr.o2 + m2];
        reinterpret_cast<float2*>(swp2)[i] = make_float2(wv, wv);
    }
    __syncthreads();

    // ---- registers: packed pairs via LDS.64 (conflict-free) ----
    u64t a1p[C1];
    {
        const u64t* su = reinterpret_cast<const u64t*>(sa1);
#pragma unroll
        for (int c = 0; c < C1; c++) a1p[c] = su[c * 32 + lane];
    }
    u64t a2p[K2P];
    {
        const u64t* su = reinterpret_cast<const u64t*>(sa2);
#pragma unroll
        for (int j = 0; j < K2P; j++)
            a2p[j] = (j < K2) ? su[(warp * K2 + j) * 32 + lane] : 0ull;
    }
    __syncthreads();   // sa dead -> sout (union) alive

    const int span4 = 4 * l3n;

    for (int m3 = 0; m3 < l3n; m3++) {
        const int u0 = m3 * WROW;    // ull index of this m3's first dup-pair
        u64t acc0 = 0, acc1 = 0, acc2 = 0, acc3 = 0;
#pragma unroll
        for (int m1 = 0; m1 < K1; m1++) {
            u64t sv = 0;
            if constexpr (K2P >= 4) {
                const ulonglong2* wp =
                    reinterpret_cast<const ulonglong2*>(swp2) + ((u0 + m1 * K2P) >> 1);
#pragma unroll
                for (int e = 0; e < K2P / 2; e++) {
                    ulonglong2 t = wp[e];            // 2 dup-pairs, broadcast
                    FMA2(sv, t.x, a2p[2 * e + 0], sv);
                    FMA2(sv, t.y, a2p[2 * e + 1], sv);
                }
            } else {
                u64t w = reinterpret_cast<const u64t*>(swp2)[u0 + m1];
                MUL2(sv, w, a2p[0]);
            }
            FMA2(acc0, a1p[0 * K1 + m1], sv, acc0);
            FMA2(acc1, a1p[1 * K1 + m1], sv, acc1);
            FMA2(acc2, a1p[2 * K1 + m1], sv, acc2);
            FMA2(acc3, a1p[3 * K1 + m1], sv, acc3);
        }
        // rows r = (u*4 + v)*l3n + m3; plane-k staging into lo/hi halves
        {
            float lo, hi;
            int r, r4, k, idx;
            r = (0 * 4 + warp) * l3n + m3; r4 = r >> 2; k = r & 3;
            idx = (k * span4 + r4) * 33 + lane;
            UNPK2(lo, hi, acc0); sout[idx] = lo; sout[idx + halfOff] = hi;
            r = (1 * 4 + warp) * l3n + m3; r4 = r >> 2; k = r & 3;
            idx = (k * span4 + r4) * 33 + lane;
            UNPK2(lo, hi, acc1); sout[idx] = lo; sout[idx + halfOff] = hi;
            r = (2 * 4 + warp) * l3n + m3; r4 = r >> 2; k = r & 3;
            idx = (k * span4 + r4) * 33 + lane;
            UNPK2(lo, hi, acc2); sout[idx] = lo; sout[idx + halfOff] = hi;
            r = (3 * 4 + warp) * l3n + m3; r4 = r >> 2; k = r & 3;
            idx = (k * span4 + r4) * 33 + lane;
            UNPK2(lo, hi, acc3); sout[idx] = lo; sout[idx + halfOff] = hi;
        }
    }
    __syncthreads();

    // ---- flat epilogue over 64 batch rows, coalesced float4 ----
    {
        const int total = 64 * span4;
        int b  = tid / span4;               // single runtime division
        int r4 = tid - b * span4;
        const int db = 128 / span4;         // block-uniform
        const int dr = 128 - db * span4;
        for (int i = tid; i < total; i += 128) {
            const float* sp = sout + (b >> 5) * halfOff;
            int bc = b & 31;
            float4 v;
            v.x = sp[(0 * span4 + r4) * 33 + bc];
            v.y = sp[(1 * span4 + r4) * 33 + bc];
            v.z = sp[(2 * span4 + r4) * 33 + bc];
            v.w = sp[(3 * span4 + r4) * 33 + bc];
            *reinterpret_cast<float4*>(
                out + (size_t)(b0 + b) * OUT_W + gr.gbase + 4 * r4) = v;
            b += db; r4 += dr;
            if (r4 >= span4) { r4 -= span4; b++; }
        }
    }
}

// ===========================================================================
// Scalar path (unchanged R8) for the big groups.
// ===========================================================================
template <int L1, int L2>
__device__ __forceinline__ void run_group(
    const Group gr,
    const float* __restrict__ in1, const float* __restrict__ in2,
    const float* __restrict__ cb,
    float* __restrict__ out, int b0,
    float* sa, float* swp)
{
    constexpr int K1 = 2 * L1 + 1, K2 = 2 * L2 + 1;
    constexpr int C1 = 4 * K1, C2 = 4 * K2;
    constexpr int Q1 = C1 / 4, Q2 = C2 / 4;
    constexpr int K2P = (K2 == 1) ? 1 : ((K2 + 3) & ~3);
    constexpr int WROW = K1 * K2P;

    float* sa1  = sa;
    float* sa2  = sa + C1 * 32;
    float* sout = sa;

    const int tid  = threadIdx.x;
    const int lane = tid & 31;
    const int warp = tid >> 5;
    const int l3n  = 2 * gr.l3 + 1;

    {
        const float4* p1 = reinterpret_cast<const float4*>(in1) + (size_t)b0 * 16 + (gr.o1 >> 2);
        for (int x = tid; x < 32 * Q1; x += 128) {
            int b = x / Q1, q = x - b * Q1;
            float4 v = p1[(size_t)b * 16 + q];
            sa1[(4 * q + 0) * 32 + b] = v.x;
            sa1[(4 * q + 1) * 32 + b] = v.y;
            sa1[(4 * q + 2) * 32 + b] = v.z;
            sa1[(4 * q + 3) * 32 + b] = v.w;
        }
        const float4* p2 = reinterpret_cast<const float4*>(in2) + (size_t)b0 * 16 + (gr.o2 >> 2);
        for (int x = tid; x < 32 * Q2; x += 128) {
            int b = x / Q2, q = x - b * Q2;
            float4 v = p2[(size_t)b * 16 + q];
            sa2[(4 * q + 0) * 32 + b] = v.x;
            sa2[(4 * q + 1) * 32 + b] = v.y;
            sa2[(4 * q + 2) * 32 + b] = v.z;
            sa2[(4 * q + 3) * 32 + b] = v.w;
        }
    }
    for (int i = tid; i < l3n * WROW; i += 128) {
        int m3 = i / WROW;
        int r  = i - m3 * WROW;
        int m1 = r / K2P;
        int m2 = r - m1 * K2P;
        float wv = 0.f;
        if (m2 < K2)
            wv = cb[(size_t)(gr.gbase + m3) * CB_W + (gr.o1 + m1) * 64 + gr.o2 + m2];
        swp[i] = wv;
    }
    __syncthreads();

    float a1[C1];
#pragma unroll
    for (int c = 0; c < C1; c++) a1[c] = sa1[c * 32 + lane];
    float a2p[K2P];
#pragma unroll
    for (int j = 0; j < K2P; j++)
        a2p[j] = (j < K2) ? sa2[(warp * K2 + j) * 32 + lane] : 0.f;
    __syncthreads();

    const int span4 = 4 * l3n;

    for (int m3 = 0; m3 < l3n; m3++) {
        const float* wr = swp + m3 * WROW;
        float acc0 = 0.f, acc1 = 0.f, acc2 = 0.f, acc3 = 0.f;
#pragma unroll
        for (int m1 = 0; m1 < K1; m1++) {
            float s = 0.f;
            if constexpr (K2P % 4 == 0) {
#pragma unroll
                for (int q = 0; q < K2P / 4; q++) {
                    float4 w4 = *reinterpret_cast<const float4*>(wr + m1 * K2P + 4 * q);
                    s += w4.x * a2p[4 * q + 0];
                    s += w4.y * a2p[4 * q + 1];
                    s += w4.z * a2p[4 * q + 2];
                    s += w4.w * a2p[4 * q + 3];
                }
            } else {
                s = wr[m1] * a2p[0];
            }
            acc0 += a1[0 * K1 + m1] * s;
            acc1 += a1[1 * K1 + m1] * s;
            acc2 += a1[2 * K1 + m1] * s;
            acc3 += a1[3 * K1 + m1] * s;
        }
        {
            int r, r4, k;
            r = (0 * 4 + warp) * l3n + m3; r4 = r >> 2; k = r & 3;
            sout[(k * span4 + r4) * 33 + lane] = acc0;
            r = (1 * 4 + warp) * l3n + m3; r4 = r >> 2; k = r & 3;
            sout[(k * span4 + r4) * 33 + lane] = acc1;
            r = (2 * 4 + warp) * l3n + m3; r4 = r >> 2; k = r & 3;
            sout[(k * span4 + r4) * 33 + lane] = acc2;
            r = (3 * 4 + warp) * l3n + m3; r4 = r >> 2; k = r & 3;
            sout[(k * span4 + r4) * 33 + lane] = acc3;
        }
    }
    __syncthreads();

    {
        const int total = 32 * span4;
        int b  = tid / span4;
        int r4 = tid - b * span4;
        const int db = 128 / span4;
        const int dr = 128 - db * span4;
        for (int i = tid; i < total; i += 128) {
            float4 v;
            v.x = sout[(0 * span4 + r4) * 33 + b];
            v.y = sout[(1 * span4 + r4) * 33 + b];
            v.z = sout[(2 * span4 + r4) * 33 + b];
            v.w = sout[(3 * span4 + r4) * 33 + b];
            *reinterpret_cast<float4*>(
                out + (size_t)(b0 + b) * OUT_W + gr.gbase + 4 * r4) = v;
            b += db; r4 += dr;
            if (r4 >= span4) { r4 -= span4; b++; }
        }
    }
}

// ---------------------------------------------------------------------------
#define SM_HALF 4752   // per-half sout floats: 4*span4max*33 = 4*36*33

__global__ void __launch_bounds__(128, 5)
tp_small(const float* __restrict__ in1, const float* __restrict__ in2,
         const float* __restrict__ cb, float* __restrict__ out)
{
    __shared__ float swp2[720];            // duplicated W: 2*360
    __shared__ float ubuf[2 * SM_HALF];    // sout lo/hi; sa unions into lo

    const Group gr = GS[blockIdx.x];
    const int b0 = blockIdx.y * 64;

#define RG(A, B2) run_group_p2<A, B2>(gr, in1, in2, cb, out, b0, ubuf, swp2, SM_HALF)
    switch (gr.l1 * 3 + gr.l2) {
        case 0: RG(0, 0); break;
        case 1: RG(0, 1); break;
        case 2: RG(0, 2); break;
        case 3: RG(1, 0); break;
        case 4: RG(1, 1); break;
        case 5: RG(1, 2); break;
        case 6: RG(2, 0); break;
        case 7: RG(2, 1); break;
        case 8: RG(2, 2); break;
    }
#undef RG
}

__global__ void __launch_bounds__(128, 7)
tp_big(const float* __restrict__ in1, const float* __restrict__ in2,
       const float* __restrict__ cb, float* __restrict__ out)
{
    __shared__ float swp[728];
    __shared__ float ubuf[6864];

    const Group gr = GB[blockIdx.x];
    const int b0 = blockIdx.y * 32;

#define RG(A, B2) run_group<A, B2>(gr, in1, in2, cb, out, b0, ubuf, swp)
    switch (gr.l1 * 4 + gr.l2) {
        case  3: RG(0, 3); break;
        case  7: RG(1, 3); break;
        case 11: RG(2, 3); break;
        case 12: RG(3, 0); break;
        case 13: RG(3, 1); break;
        case 14: RG(3, 2); break;
        case 15: RG(3, 3); break;
    }
#undef RG
}

// ---------------------------------------------------------------------------
// Fork-join launch -> two parallel graph branches, concurrent execution.
// ---------------------------------------------------------------------------
extern "C" void kernel_launch(void* const* d_in, const int* in_sizes, int n_in,
                              void* d_out, int out_size)
{
    const float* in1 = (const float*)d_in[0];
    const float* in2 = (const float*)d_in[1];
    const float* cb  = (const float*)d_in[2];
    float* out = (float*)d_out;

    int B = in_sizes[0] / 64;

    cudaStream_t s2;
    cudaStreamCreateWithFlags(&s2, cudaStreamNonBlocking);
    cudaEvent_t eFork, eJoin;
    cudaEventCreateWithFlags(&eFork, cudaEventDisableTiming);
    cudaEventCreateWithFlags(&eJoin, cudaEventDisableTiming);

    cudaEventRecord(eFork, 0);
    cudaStreamWaitEvent(s2, eFork, 0);

    dim3 grid_big(N_BIG, B / 32);
    tp_big<<<grid_big, 128, 0, 0>>>(in1, in2, cb, out);
    dim3 grid_small(N_SMALL, B / 64);
    tp_small<<<grid_small, 128, 0, s2>>>(in1, in2, cb, out);

    cudaEventRecord(eJoin, s2);
    cudaStreamWaitEvent(0, eJoin, 0);

    cudaEventDestroy(eFork);
    cudaEventDestroy(eJoin);
    cudaStreamDestroy(s2);
}